// round 4
// baseline (speedup 1.0000x reference)
#include <cuda_runtime.h>
#include <cstdint>
#include <cstddef>

// ============================================================================
// LSTM: x (32,512,1024), h0 (32,1024), Wx (1024,4096), Wh (1024,4096), b (4096)
// Phase 1: g_xproj = x @ Wx + b   (tf32 mma.sync, 128x128x16 pipeline)
// Phase 2: ONE persistent kernel, 128 co-resident CTAs, Wh slice resident in
//          SMEM (tf32). h staged via 3-deep cp.async pipeline. Flag-array
//          grid barrier (parallel release stores, monotonic, relaxed polls).
// ============================================================================

#define DI __device__ __forceinline__

DI uint32_t smem_u32(const void* p) { return (uint32_t)__cvta_generic_to_shared(p); }

DI void cp16(const void* smem_dst, const void* gsrc) {
    asm volatile("cp.async.ca.shared.global [%0], [%1], 16;"
                 :: "r"(smem_u32(smem_dst)), "l"(gsrc));
}
DI void cp16cg(const void* smem_dst, const void* gsrc) {
    asm volatile("cp.async.cg.shared.global [%0], [%1], 16;"
                 :: "r"(smem_u32(smem_dst)), "l"(gsrc));
}
DI void cp_commit() { asm volatile("cp.async.commit_group;"); }
template<int N> DI void cp_wait() { asm volatile("cp.async.wait_group %0;" :: "n"(N)); }

DI uint32_t f2tf32(float f) {
    uint32_t u;
    asm("cvt.rna.tf32.f32 %0, %1;" : "=r"(u) : "f"(f));
    return u;
}

DI unsigned ld_rlx_gpu(const unsigned* p) {
    unsigned v;
    asm volatile("ld.relaxed.gpu.u32 %0, [%1];" : "=r"(v) : "l"(p));
    return v;
}
DI void fence_acqrel_gpu() { asm volatile("fence.acq_rel.gpu;" ::: "memory"); }
DI void st_rel_gpu(unsigned* p, unsigned v) {
    asm volatile("st.release.gpu.u32 [%0], %1;" :: "l"(p), "r"(v) : "memory");
}

DI void mma_tf32(float* c, const uint32_t* a, const uint32_t* b) {
    asm volatile(
        "mma.sync.aligned.m16n8k8.row.col.f32.tf32.tf32.f32 "
        "{%0,%1,%2,%3}, {%4,%5,%6,%7}, {%8,%9}, {%0,%1,%2,%3};"
        : "+f"(c[0]), "+f"(c[1]), "+f"(c[2]), "+f"(c[3])
        : "r"(a[0]), "r"(a[1]), "r"(a[2]), "r"(a[3]), "r"(b[0]), "r"(b[1]));
}

// Scratch (allocation-free rule: __device__ globals)
__device__ float g_xproj[16384 * 4096];   // 256 MB: (N*T, 4H)
__device__ unsigned g_flags[128 * 32];    // per-CTA barrier flags, 128B apart

// ----------------------------------------------------------------------------
// Phase 1: xproj = X(16384x1024) @ Wx(1024x4096) + b
// ----------------------------------------------------------------------------
__global__ void __launch_bounds__(256) xproj_kernel(
    const float* __restrict__ X, const float* __restrict__ Wx,
    const float* __restrict__ bias)
{
    __shared__ float sA[2][128][20];
    __shared__ float sB[2][16][136];

    const int tid   = threadIdx.x;
    const int mBase = blockIdx.y * 128;
    const int nBase = blockIdx.x * 128;

    auto load_stage = [&](int s, int k0) {
#pragma unroll
        for (int i = tid; i < 512; i += 256) {
            int r = i >> 2, c = (i & 3) << 2;
            cp16(&sA[s][r][c], X + (size_t)(mBase + r) * 1024 + k0 + c);
        }
#pragma unroll
        for (int i = tid; i < 512; i += 256) {
            int r = i >> 5, c = (i & 31) << 2;
            cp16(&sB[s][r][c], Wx + (size_t)(k0 + r) * 4096 + nBase + c);
        }
        cp_commit();
    };

    load_stage(0, 0);

    const int warp = tid >> 5, lane = tid & 31;
    const int wm = (warp >> 2) * 64, wn = (warp & 3) * 32;
    const int gid = lane >> 2, tig = lane & 3;

    float acc[4][4][4];
#pragma unroll
    for (int mi = 0; mi < 4; ++mi)
#pragma unroll
        for (int ni = 0; ni < 4; ++ni)
#pragma unroll
            for (int r = 0; r < 4; ++r) acc[mi][ni][r] = 0.f;

    for (int kt = 0; kt < 64; ++kt) {
        const int cur = kt & 1;
        cp_wait<0>();
        __syncthreads();
        if (kt < 63) load_stage(cur ^ 1, (kt + 1) * 16);

#pragma unroll
        for (int kk = 0; kk < 16; kk += 8) {
            uint32_t af[4][4], bf[4][2];
#pragma unroll
            for (int mi = 0; mi < 4; ++mi) {
                int r = wm + mi * 16 + gid;
                af[mi][0] = f2tf32(sA[cur][r][kk + tig]);
                af[mi][1] = f2tf32(sA[cur][r + 8][kk + tig]);
                af[mi][2] = f2tf32(sA[cur][r][kk + tig + 4]);
                af[mi][3] = f2tf32(sA[cur][r + 8][kk + tig + 4]);
            }
#pragma unroll
            for (int ni = 0; ni < 4; ++ni) {
                int cc = wn + ni * 8 + gid;
                bf[ni][0] = f2tf32(sB[cur][kk + tig][cc]);
                bf[ni][1] = f2tf32(sB[cur][kk + tig + 4][cc]);
            }
#pragma unroll
            for (int mi = 0; mi < 4; ++mi)
#pragma unroll
                for (int ni = 0; ni < 4; ++ni)
                    mma_tf32(acc[mi][ni], af[mi], bf[ni]);
        }
    }

#pragma unroll
    for (int mi = 0; mi < 4; ++mi) {
#pragma unroll
        for (int ni = 0; ni < 4; ++ni) {
            int row = mBase + wm + mi * 16 + gid;
            int col = nBase + wn + ni * 8 + tig * 2;
            float b0 = bias[col], b1 = bias[col + 1];
            float* p0 = g_xproj + (size_t)row * 4096 + col;
            p0[0] = acc[mi][ni][0] + b0;
            p0[1] = acc[mi][ni][1] + b1;
            float* p1 = g_xproj + (size_t)(row + 8) * 4096 + col;
            p1[0] = acc[mi][ni][2] + b0;
            p1[1] = acc[mi][ni][3] + b1;
        }
    }
}

// ----------------------------------------------------------------------------
__global__ void init_kernel() {
    int i = blockIdx.x * 256 + threadIdx.x;
    if (i < 128 * 32) g_flags[i] = 0u;
}

// ----------------------------------------------------------------------------
// Phase 2: persistent recurrence.
// SMEM: sWh (tf32, 1024x32, stride 40) = 160 KB resident.
//       sH 3-stage pipeline, 32x132 fp32/stage (conflict-free) = 50.7 KB,
//       aliased by partials 8x32x33 after the mma loop.
// ----------------------------------------------------------------------------
static const int SWH_BYTES   = 1024 * 40 * 4;                 // 163840
static const int STAGE_BYTES = 32 * 132 * 4;                  // 16896
static const int SMEM_BYTES  = SWH_BYTES + 3 * STAGE_BYTES;   // 214528

__global__ void __launch_bounds__(256, 1) lstm_persist(
    const float* __restrict__ Wh, const float* __restrict__ h0,
    float* __restrict__ out)
{
    extern __shared__ __align__(16) char dyn[];
    uint32_t (*sWh)[40]   = reinterpret_cast<uint32_t (*)[40]>(dyn);
    float (*sH)[32][132]  = reinterpret_cast<float (*)[32][132]>(dyn + SWH_BYTES);
    float (*part)[32][33] = reinterpret_cast<float (*)[32][33]>(dyn + SWH_BYTES);

    const int tid = threadIdx.x;
    const int c8  = blockIdx.x * 8;

    // One-time: resident Wh slice, pre-converted to tf32.
    for (int idx = tid; idx < 1024 * 32; idx += 256) {
        int row = idx >> 5, col = idx & 31;
        int q = col >> 3, jj = col & 7;
        sWh[row][col] = f2tf32(__ldg(Wh + (size_t)row * 4096 + q * 1024 + c8 + jj));
    }
    __syncthreads();

    const int warp = tid >> 5, lane = tid & 31;
    const int gid = lane >> 2, tig = lane & 3;
    const int kw = warp * 16;                  // warp's k-cols within a chunk
    // Epilogue cell mapping (conflict-free partial reduce: bb varies per lane)
    const int jb = tid >> 5;                   // gate sub-col 0..7 (== warp)
    const int bb = tid & 31;                   // batch row 0..31

    float creg = 0.f;

    for (int t = 0; t < 512; ++t) {
        const float* hp;
        size_t hstride;
        if (t == 0) { hp = h0;                           hstride = 1024; }
        else        { hp = out + (size_t)(t - 1) * 1024; hstride = (size_t)512 * 1024; }

        // Prefetch xproj for this thread (hidden behind the mma loop)
        const float* xpp = g_xproj + ((size_t)bb * 512 + t) * 4096 + c8 + jb;
        float xp0 = __ldg(xpp);
        float xp1 = __ldg(xpp + 1024);
        float xp2 = __ldg(xpp + 2048);
        float xp3 = __ldg(xpp + 3072);

        auto load_h = [&](int s, int k0) {
#pragma unroll
            for (int i = tid; i < 1024; i += 256) {
                int r = i >> 5, c = (i & 31) << 2;
                cp16cg(&sH[s][r][c], hp + (size_t)r * hstride + k0 + c);
            }
            cp_commit();
        };
        load_h(0, 0);
        load_h(1, 128);

        float acc[2][4][4];
#pragma unroll
        for (int mi = 0; mi < 2; ++mi)
#pragma unroll
            for (int ni = 0; ni < 4; ++ni)
#pragma unroll
                for (int r = 0; r < 4; ++r) acc[mi][ni][r] = 0.f;

        for (int ch = 0; ch < 8; ++ch) {
            const int cur = ch % 3;
            if (ch < 7) cp_wait<1>(); else cp_wait<0>();
            __syncthreads();
            if (ch < 6) load_h((ch + 2) % 3, (ch + 2) * 128);

#pragma unroll
            for (int sub = 0; sub < 2; ++sub) {
                const int kk = kw + sub * 8;       // col within 128-chunk
                const int kg = ch * 128 + kk;      // global k (Wh row)
                uint32_t af[2][4], bf[4][2];
#pragma unroll
                for (int mi = 0; mi < 2; ++mi) {
                    int r = mi * 16 + gid;
                    af[mi][0] = f2tf32(sH[cur][r][kk + tig]);
                    af[mi][1] = f2tf32(sH[cur][r + 8][kk + tig]);
                    af[mi][2] = f2tf32(sH[cur][r][kk + tig + 4]);
                    af[mi][3] = f2tf32(sH[cur][r + 8][kk + tig + 4]);
                }
#pragma unroll
                for (int ni = 0; ni < 4; ++ni) {
                    bf[ni][0] = sWh[kg + tig][ni * 8 + gid];
                    bf[ni][1] = sWh[kg + tig + 4][ni * 8 + gid];
                }
#pragma unroll
                for (int mi = 0; mi < 2; ++mi)
#pragma unroll
                    for (int ni = 0; ni < 4; ++ni)
                        mma_tf32(acc[mi][ni], af[mi], bf[ni]);
            }
        }

        __syncthreads();   // all cp drained; safe to alias partials over sH

#pragma unroll
        for (int mi = 0; mi < 2; ++mi)
#pragma unroll
            for (int ni = 0; ni < 4; ++ni) {
                int r = mi * 16 + gid, c = ni * 8 + tig * 2;
                part[warp][r][c]         = acc[mi][ni][0];
                part[warp][r][c + 1]     = acc[mi][ni][1];
                part[warp][r + 8][c]     = acc[mi][ni][2];
                part[warp][r + 8][c + 1] = acc[mi][ni][3];
            }
        __syncthreads();

        // Reduce partials + xproj -> gates -> cell -> h_t
        float pre[4] = {xp0, xp1, xp2, xp3};
#pragma unroll
        for (int q = 0; q < 4; ++q) {
            int c = q * 8 + jb;
            float s = 0.f;
#pragma unroll
            for (int w = 0; w < 8; ++w) s += part[w][bb][c];
            pre[q] += s;
        }
        float ig = 1.f / (1.f + expf(-pre[0]));
        float fg = 1.f / (1.f + expf(-pre[1]));
        float og = 1.f / (1.f + expf(-pre[2]));
        float gg = tanhf(pre[3]);
        creg = fg * creg + ig * gg;
        out[((size_t)bb * 512 + t) * 1024 + c8 + jb] = og * tanhf(creg);

        // ---- Flag-array grid barrier (monotonic; relaxed polls + one fence) --
        __threadfence();
        __syncthreads();
        if (tid == 0) st_rel_gpu(&g_flags[blockIdx.x * 32], (unsigned)(t + 1));
        if (tid < 128) {
            const unsigned target = (unsigned)(t + 1);
            while (ld_rlx_gpu(&g_flags[tid * 32]) < target) { }
        }
        fence_acqrel_gpu();
        __syncthreads();
    }
}

// ----------------------------------------------------------------------------
extern "C" void kernel_launch(void* const* d_in, const int* in_sizes, int n_in,
                              void* d_out, int out_size)
{
    const float* x  = (const float*)d_in[0];   // (32,512,1024)
    const float* h0 = (const float*)d_in[1];   // (32,1024)
    const float* Wx = (const float*)d_in[2];   // (1024,4096)
    const float* Wh = (const float*)d_in[3];   // (1024,4096)
    const float* b  = (const float*)d_in[4];   // (4096,)
    float* out = (float*)d_out;                // (32,512,1024)

    cudaFuncSetAttribute(lstm_persist,
                         cudaFuncAttributeMaxDynamicSharedMemorySize, SMEM_BYTES);

    dim3 gA(32, 128);
    xproj_kernel<<<gA, 256>>>(x, Wx, b);
    init_kernel<<<16, 256>>>();
    lstm_persist<<<128, 256, SMEM_BYTES>>>(Wh, h0, out);
}

// round 6
// speedup vs baseline: 1.0912x; 1.0912x over previous
#include <cuda_runtime.h>
#include <cstdint>
#include <cstddef>

// ============================================================================
// LSTM: x (32,512,1024), h0 (32,1024), Wx (1024,4096), Wh (1024,4096), b (4096)
// Phase 1: g_xproj = x @ Wx + b   (tf32 mma.sync, 128x128x16 pipeline)
// Phase 2: ONE persistent kernel, 128 co-resident CTAs, Wh slice resident in
//          SMEM (tf32). h staged via 4-stage cp.async pipeline (3 preloaded,
//          wait_group 2). Hierarchical grid barrier: parallel flag stores ->
//          CTA0 aggregates -> single epoch word polled by 1 thread/CTA.
// ============================================================================

#define DI __device__ __forceinline__

DI uint32_t smem_u32(const void* p) { return (uint32_t)__cvta_generic_to_shared(p); }

DI void cp16(const void* smem_dst, const void* gsrc) {
    asm volatile("cp.async.ca.shared.global [%0], [%1], 16;"
                 :: "r"(smem_u32(smem_dst)), "l"(gsrc));
}
DI void cp16cg(const void* smem_dst, const void* gsrc) {
    asm volatile("cp.async.cg.shared.global [%0], [%1], 16;"
                 :: "r"(smem_u32(smem_dst)), "l"(gsrc));
}
DI void cp_commit() { asm volatile("cp.async.commit_group;"); }
template<int N> DI void cp_wait() { asm volatile("cp.async.wait_group %0;" :: "n"(N)); }

DI uint32_t f2tf32(float f) {
    uint32_t u;
    asm("cvt.rna.tf32.f32 %0, %1;" : "=r"(u) : "f"(f));
    return u;
}

DI unsigned ld_acq_gpu(const unsigned* p) {
    unsigned v;
    asm volatile("ld.acquire.gpu.u32 %0, [%1];" : "=r"(v) : "l"(p));
    return v;
}
DI void st_rel_gpu(unsigned* p, unsigned v) {
    asm volatile("st.release.gpu.u32 [%0], %1;" :: "l"(p), "r"(v) : "memory");
}

DI void mma_tf32(float* c, const uint32_t* a, const uint32_t* b) {
    asm volatile(
        "mma.sync.aligned.m16n8k8.row.col.f32.tf32.tf32.f32 "
        "{%0,%1,%2,%3}, {%4,%5,%6,%7}, {%8,%9}, {%0,%1,%2,%3};"
        : "+f"(c[0]), "+f"(c[1]), "+f"(c[2]), "+f"(c[3])
        : "r"(a[0]), "r"(a[1]), "r"(a[2]), "r"(a[3]), "r"(b[0]), "r"(b[1]));
}

DI float fast_sigmoid(float x) { return 1.f / (1.f + __expf(-x)); }
DI float fast_tanh(float x) {
    float e = __expf(-2.f * x);
    return (1.f - e) / (1.f + e);
}

// Scratch (allocation-free rule: __device__ globals)
__device__ float g_xproj[16384 * 4096];   // 256 MB: (N*T, 4H)
__device__ unsigned g_flags[128 * 32];    // per-CTA arrival flags, 128B apart
__device__ unsigned g_epoch[32];          // aggregated epoch (single word used)

// ----------------------------------------------------------------------------
// Phase 1: xproj = X(16384x1024) @ Wx(1024x4096) + b
// ----------------------------------------------------------------------------
__global__ void __launch_bounds__(256) xproj_kernel(
    const float* __restrict__ X, const float* __restrict__ Wx,
    const float* __restrict__ bias)
{
    __shared__ float sA[2][128][20];
    __shared__ float sB[2][16][136];

    const int tid   = threadIdx.x;
    const int mBase = blockIdx.y * 128;
    const int nBase = blockIdx.x * 128;

    auto load_stage = [&](int s, int k0) {
#pragma unroll
        for (int i = tid; i < 512; i += 256) {
            int r = i >> 2, c = (i & 3) << 2;
            cp16(&sA[s][r][c], X + (size_t)(mBase + r) * 1024 + k0 + c);
        }
#pragma unroll
        for (int i = tid; i < 512; i += 256) {
            int r = i >> 5, c = (i & 31) << 2;
            cp16(&sB[s][r][c], Wx + (size_t)(k0 + r) * 4096 + nBase + c);
        }
        cp_commit();
    };

    load_stage(0, 0);

    const int warp = tid >> 5, lane = tid & 31;
    const int wm = (warp >> 2) * 64, wn = (warp & 3) * 32;
    const int gid = lane >> 2, tig = lane & 3;

    float acc[4][4][4];
#pragma unroll
    for (int mi = 0; mi < 4; ++mi)
#pragma unroll
        for (int ni = 0; ni < 4; ++ni)
#pragma unroll
            for (int r = 0; r < 4; ++r) acc[mi][ni][r] = 0.f;

    for (int kt = 0; kt < 64; ++kt) {
        const int cur = kt & 1;
        cp_wait<0>();
        __syncthreads();
        if (kt < 63) load_stage(cur ^ 1, (kt + 1) * 16);

#pragma unroll
        for (int kk = 0; kk < 16; kk += 8) {
            uint32_t af[4][4], bf[4][2];
#pragma unroll
            for (int mi = 0; mi < 4; ++mi) {
                int r = wm + mi * 16 + gid;
                af[mi][0] = f2tf32(sA[cur][r][kk + tig]);
                af[mi][1] = f2tf32(sA[cur][r + 8][kk + tig]);
                af[mi][2] = f2tf32(sA[cur][r][kk + tig + 4]);
                af[mi][3] = f2tf32(sA[cur][r + 8][kk + tig + 4]);
            }
#pragma unroll
            for (int ni = 0; ni < 4; ++ni) {
                int cc = wn + ni * 8 + gid;
                bf[ni][0] = f2tf32(sB[cur][kk + tig][cc]);
                bf[ni][1] = f2tf32(sB[cur][kk + tig + 4][cc]);
            }
#pragma unroll
            for (int mi = 0; mi < 4; ++mi)
#pragma unroll
                for (int ni = 0; ni < 4; ++ni)
                    mma_tf32(acc[mi][ni], af[mi], bf[ni]);
        }
    }

#pragma unroll
    for (int mi = 0; mi < 4; ++mi) {
#pragma unroll
        for (int ni = 0; ni < 4; ++ni) {
            int row = mBase + wm + mi * 16 + gid;
            int col = nBase + wn + ni * 8 + tig * 2;
            float b0 = bias[col], b1 = bias[col + 1];
            float* p0 = g_xproj + (size_t)row * 4096 + col;
            p0[0] = acc[mi][ni][0] + b0;
            p0[1] = acc[mi][ni][1] + b1;
            float* p1 = g_xproj + (size_t)(row + 8) * 4096 + col;
            p1[0] = acc[mi][ni][2] + b0;
            p1[1] = acc[mi][ni][3] + b1;
        }
    }
}

// ----------------------------------------------------------------------------
__global__ void init_kernel() {
    int i = blockIdx.x * 256 + threadIdx.x;
    if (i < 128 * 32) g_flags[i] = 0u;
    if (i < 32) g_epoch[i] = 0u;
}

// ----------------------------------------------------------------------------
// Phase 2: persistent recurrence.
// SMEM: sWh (tf32, 1024x32, stride 40) = 160 KB resident.
//       sH: 4 stages x 32x132 fp32 (conflict-free) = 66 KB,
//       aliased after the mma loop by partials 8x32x40 (40 KB, conflict-free).
// ----------------------------------------------------------------------------
static const int SWH_BYTES   = 1024 * 40 * 4;                 // 163840
static const int STAGE_BYTES = 32 * 132 * 4;                  // 16896
static const int SMEM_BYTES  = SWH_BYTES + 4 * STAGE_BYTES;   // 231424

__global__ void __launch_bounds__(256, 1) lstm_persist(
    const float* __restrict__ Wh, const float* __restrict__ h0,
    float* __restrict__ out)
{
    extern __shared__ __align__(16) char dyn[];
    uint32_t (*sWh)[40]   = reinterpret_cast<uint32_t (*)[40]>(dyn);
    float (*sH)[32][132]  = reinterpret_cast<float (*)[32][132]>(dyn + SWH_BYTES);
    float (*part)[32][40] = reinterpret_cast<float (*)[32][40]>(dyn + SWH_BYTES);

    const int tid = threadIdx.x;
    const int cta = blockIdx.x;
    const int c8  = cta * 8;

    // One-time: resident Wh slice, pre-converted to tf32.
    for (int idx = tid; idx < 1024 * 32; idx += 256) {
        int row = idx >> 5, col = idx & 31;
        int q = col >> 3, jj = col & 7;
        sWh[row][col] = f2tf32(__ldg(Wh + (size_t)row * 4096 + q * 1024 + c8 + jj));
    }
    __syncthreads();

    const int warp = tid >> 5, lane = tid & 31;
    const int gid = lane >> 2, tig = lane & 3;
    const int kw = warp * 16;                  // warp's k-cols within a chunk
    // Epilogue cell mapping (coalesced h store: j consecutive within warp)
    const int bb = tid >> 3;                   // batch row 0..31
    const int jb = tid & 7;                    // gate sub-col 0..7

    float creg = 0.f;

    for (int t = 0; t < 512; ++t) {
        const float* hp;
        size_t hstride;
        if (t == 0) { hp = h0;                           hstride = 1024; }
        else        { hp = out + (size_t)(t - 1) * 1024; hstride = (size_t)512 * 1024; }

        // Prefetch xproj for this thread (consumed at epilogue)
        const float* xpp = g_xproj + ((size_t)bb * 512 + t) * 4096 + c8 + jb;
        float xp0 = __ldg(xpp);
        float xp1 = __ldg(xpp + 1024);
        float xp2 = __ldg(xpp + 2048);
        float xp3 = __ldg(xpp + 3072);

        auto load_h = [&](int s, int k0) {
#pragma unroll
            for (int i = tid; i < 1024; i += 256) {
                int r = i >> 5, c = (i & 31) << 2;
                cp16cg(&sH[s][r][c], hp + (size_t)r * hstride + k0 + c);
            }
            cp_commit();
        };
        load_h(0, 0);
        load_h(1, 128);
        load_h(2, 256);

        float acc[2][4][4];
#pragma unroll
        for (int mi = 0; mi < 2; ++mi)
#pragma unroll
            for (int ni = 0; ni < 4; ++ni)
#pragma unroll
                for (int r = 0; r < 4; ++r) acc[mi][ni][r] = 0.f;

        for (int ch = 0; ch < 8; ++ch) {
            const int cur = ch & 3;
            if (ch < 6) cp_wait<2>(); else cp_wait<0>();
            __syncthreads();
            if (ch < 5) load_h((ch + 3) & 3, (ch + 3) * 128);

#pragma unroll
            for (int sub = 0; sub < 2; ++sub) {
                const int kk = kw + sub * 8;       // col within 128-chunk
                const int kg = ch * 128 + kk;      // global k (Wh row)
                uint32_t af[2][4], bf[4][2];
#pragma unroll
                for (int mi = 0; mi < 2; ++mi) {
                    int r = mi * 16 + gid;
                    af[mi][0] = f2tf32(sH[cur][r][kk + tig]);
                    af[mi][1] = f2tf32(sH[cur][r + 8][kk + tig]);
                    af[mi][2] = f2tf32(sH[cur][r][kk + tig + 4]);
                    af[mi][3] = f2tf32(sH[cur][r + 8][kk + tig + 4]);
                }
#pragma unroll
                for (int ni = 0; ni < 4; ++ni) {
                    bf[ni][0] = sWh[kg + tig][ni * 8 + gid];
                    bf[ni][1] = sWh[kg + tig + 4][ni * 8 + gid];
                }
#pragma unroll
                for (int mi = 0; mi < 2; ++mi)
#pragma unroll
                    for (int ni = 0; ni < 4; ++ni)
                        mma_tf32(acc[mi][ni], af[mi], bf[ni]);
            }
        }

        __syncthreads();   // all cp drained & consumed; safe to alias partials

#pragma unroll
        for (int mi = 0; mi < 2; ++mi)
#pragma unroll
            for (int ni = 0; ni < 4; ++ni) {
                int r = mi * 16 + gid, c = ni * 8 + tig * 2;
                part[warp][r][c]         = acc[mi][ni][0];
                part[warp][r][c + 1]     = acc[mi][ni][1];
                part[warp][r + 8][c]     = acc[mi][ni][2];
                part[warp][r + 8][c + 1] = acc[mi][ni][3];
            }
        __syncthreads();

        // Reduce partials + xproj -> gates -> cell -> h_t
        // LDS banking: (bb*40 + q*8 + jb) mod 32 = (8*bb + jb + 8q) mod 32:
        // per warp bb spans 4 values, jb 8 values -> all 32 banks distinct.
        float pre[4] = {xp0, xp1, xp2, xp3};
#pragma unroll
        for (int q = 0; q < 4; ++q) {
            int c = q * 8 + jb;
            float s = 0.f;
#pragma unroll
            for (int w = 0; w < 8; ++w) s += part[w][bb][c];
            pre[q] += s;
        }
        float ig = fast_sigmoid(pre[0]);
        float fg = fast_sigmoid(pre[1]);
        float og = fast_sigmoid(pre[2]);
        float gg = fast_tanh(pre[3]);
        creg = fg * creg + ig * gg;
        out[((size_t)bb * 512 + t) * 1024 + c8 + jb] = og * fast_tanh(creg);

        // ---- Hierarchical grid barrier ----
        __threadfence();
        __syncthreads();
        const unsigned target = (unsigned)(t + 1);
        if (tid == 0) st_rel_gpu(&g_flags[cta * 32], target);
        if (cta == 0) {
            if (tid < 128) {
                while (ld_acq_gpu(&g_flags[tid * 32]) < target) { }
            }
            __syncthreads();
            if (tid == 0) st_rel_gpu(&g_epoch[0], target);
        }
        if (tid == 0) {
            while (ld_acq_gpu(&g_epoch[0]) < target) { }
        }
        __syncthreads();
    }
}

// ----------------------------------------------------------------------------
extern "C" void kernel_launch(void* const* d_in, const int* in_sizes, int n_in,
                              void* d_out, int out_size)
{
    const float* x  = (const float*)d_in[0];   // (32,512,1024)
    const float* h0 = (const float*)d_in[1];   // (32,1024)
    const float* Wx = (const float*)d_in[2];   // (1024,4096)
    const float* Wh = (const float*)d_in[3];   // (1024,4096)
    const float* b  = (const float*)d_in[4];   // (4096,)
    float* out = (float*)d_out;                // (32,512,1024)

    cudaFuncSetAttribute(lstm_persist,
                         cudaFuncAttributeMaxDynamicSharedMemorySize, SMEM_BYTES);

    dim3 gA(32, 128);
    xproj_kernel<<<gA, 256>>>(x, Wx, b);
    init_kernel<<<16, 256>>>();
    lstm_persist<<<128, 256, SMEM_BYTES>>>(Wh, h0, out);
}

// round 7
// speedup vs baseline: 1.0913x; 1.0000x over previous
#include <cuda_runtime.h>
#include <cstdint>
#include <cstddef>

// ============================================================================
// LSTM: x (32,512,1024), h0 (32,1024), Wx (1024,4096), Wh (1024,4096), b (4096)
// Phase 1: g_xproj = x @ Wx + b   (tf32 mma.sync, 128x128x16 pipeline)
// Phase 2: ONE persistent kernel, 128 co-resident CTAs, Wh slice resident in
//          SMEM (tf32). NO global barrier: dataflow sync via per-CTA monotonic
//          flags. Each thread polls the single producer CTA of its cp.async
//          column before issuing; chunk order staggered per CTA so each CTA
//          starts on its own (already-published) cohort.
// ============================================================================

#define DI __device__ __forceinline__

DI uint32_t smem_u32(const void* p) { return (uint32_t)__cvta_generic_to_shared(p); }

DI void cp16(const void* smem_dst, const void* gsrc) {
    asm volatile("cp.async.ca.shared.global [%0], [%1], 16;"
                 :: "r"(smem_u32(smem_dst)), "l"(gsrc));
}
DI void cp16cg(const void* smem_dst, const void* gsrc) {
    asm volatile("cp.async.cg.shared.global [%0], [%1], 16;"
                 :: "r"(smem_u32(smem_dst)), "l"(gsrc));
}
DI void cp_commit() { asm volatile("cp.async.commit_group;"); }
template<int N> DI void cp_wait() { asm volatile("cp.async.wait_group %0;" :: "n"(N)); }

DI uint32_t f2tf32(float f) {
    uint32_t u;
    asm("cvt.rna.tf32.f32 %0, %1;" : "=r"(u) : "f"(f));
    return u;
}

DI unsigned ld_acq_gpu(const unsigned* p) {
    unsigned v;
    asm volatile("ld.acquire.gpu.u32 %0, [%1];" : "=r"(v) : "l"(p));
    return v;
}
DI void st_rel_gpu(unsigned* p, unsigned v) {
    asm volatile("st.release.gpu.u32 [%0], %1;" :: "l"(p), "r"(v) : "memory");
}

DI void mma_tf32(float* c, const uint32_t* a, const uint32_t* b) {
    asm volatile(
        "mma.sync.aligned.m16n8k8.row.col.f32.tf32.tf32.f32 "
        "{%0,%1,%2,%3}, {%4,%5,%6,%7}, {%8,%9}, {%0,%1,%2,%3};"
        : "+f"(c[0]), "+f"(c[1]), "+f"(c[2]), "+f"(c[3])
        : "r"(a[0]), "r"(a[1]), "r"(a[2]), "r"(a[3]), "r"(b[0]), "r"(b[1]));
}

DI float fast_sigmoid(float x) { return 1.f / (1.f + __expf(-x)); }
DI float fast_tanh(float x) {
    float e = __expf(-2.f * x);
    return (1.f - e) / (1.f + e);
}

// Scratch (allocation-free rule: __device__ globals)
__device__ float g_xproj[16384 * 4096];   // 256 MB: (N*T, 4H)
__device__ unsigned g_flags[128 * 32];    // per-CTA completed-step counters, 128B apart

// ----------------------------------------------------------------------------
// Phase 1: xproj = X(16384x1024) @ Wx(1024x4096) + b
// ----------------------------------------------------------------------------
__global__ void __launch_bounds__(256) xproj_kernel(
    const float* __restrict__ X, const float* __restrict__ Wx,
    const float* __restrict__ bias)
{
    __shared__ float sA[2][128][20];
    __shared__ float sB[2][16][136];

    const int tid   = threadIdx.x;
    const int mBase = blockIdx.y * 128;
    const int nBase = blockIdx.x * 128;

    auto load_stage = [&](int s, int k0) {
#pragma unroll
        for (int i = tid; i < 512; i += 256) {
            int r = i >> 2, c = (i & 3) << 2;
            cp16(&sA[s][r][c], X + (size_t)(mBase + r) * 1024 + k0 + c);
        }
#pragma unroll
        for (int i = tid; i < 512; i += 256) {
            int r = i >> 5, c = (i & 31) << 2;
            cp16(&sB[s][r][c], Wx + (size_t)(k0 + r) * 4096 + nBase + c);
        }
        cp_commit();
    };

    load_stage(0, 0);

    const int warp = tid >> 5, lane = tid & 31;
    const int wm = (warp >> 2) * 64, wn = (warp & 3) * 32;
    const int gid = lane >> 2, tig = lane & 3;

    float acc[4][4][4];
#pragma unroll
    for (int mi = 0; mi < 4; ++mi)
#pragma unroll
        for (int ni = 0; ni < 4; ++ni)
#pragma unroll
            for (int r = 0; r < 4; ++r) acc[mi][ni][r] = 0.f;

    for (int kt = 0; kt < 64; ++kt) {
        const int cur = kt & 1;
        cp_wait<0>();
        __syncthreads();
        if (kt < 63) load_stage(cur ^ 1, (kt + 1) * 16);

#pragma unroll
        for (int kk = 0; kk < 16; kk += 8) {
            uint32_t af[4][4], bf[4][2];
#pragma unroll
            for (int mi = 0; mi < 4; ++mi) {
                int r = wm + mi * 16 + gid;
                af[mi][0] = f2tf32(sA[cur][r][kk + tig]);
                af[mi][1] = f2tf32(sA[cur][r + 8][kk + tig]);
                af[mi][2] = f2tf32(sA[cur][r][kk + tig + 4]);
                af[mi][3] = f2tf32(sA[cur][r + 8][kk + tig + 4]);
            }
#pragma unroll
            for (int ni = 0; ni < 4; ++ni) {
                int cc = wn + ni * 8 + gid;
                bf[ni][0] = f2tf32(sB[cur][kk + tig][cc]);
                bf[ni][1] = f2tf32(sB[cur][kk + tig + 4][cc]);
            }
#pragma unroll
            for (int mi = 0; mi < 4; ++mi)
#pragma unroll
                for (int ni = 0; ni < 4; ++ni)
                    mma_tf32(acc[mi][ni], af[mi], bf[ni]);
        }
    }

#pragma unroll
    for (int mi = 0; mi < 4; ++mi) {
#pragma unroll
        for (int ni = 0; ni < 4; ++ni) {
            int row = mBase + wm + mi * 16 + gid;
            int col = nBase + wn + ni * 8 + tig * 2;
            float b0 = bias[col], b1 = bias[col + 1];
            float* p0 = g_xproj + (size_t)row * 4096 + col;
            p0[0] = acc[mi][ni][0] + b0;
            p0[1] = acc[mi][ni][1] + b1;
            float* p1 = g_xproj + (size_t)(row + 8) * 4096 + col;
            p1[0] = acc[mi][ni][2] + b0;
            p1[1] = acc[mi][ni][3] + b1;
        }
    }
}

// ----------------------------------------------------------------------------
__global__ void init_kernel() {
    int i = blockIdx.x * 256 + threadIdx.x;
    if (i < 128 * 32) g_flags[i] = 0u;
}

// ----------------------------------------------------------------------------
// Phase 2: persistent recurrence, dataflow-synchronized.
// SMEM: sWh (tf32, 1024x32, stride 40) = 160 KB resident.
//       sH: 4 stages x 32x132 fp32 = 66 KB, aliased by partials 8x32x40.
// ----------------------------------------------------------------------------
static const int SWH_BYTES   = 1024 * 40 * 4;                 // 163840
static const int STAGE_BYTES = 32 * 132 * 4;                  // 16896
static const int SMEM_BYTES  = SWH_BYTES + 4 * STAGE_BYTES;   // 231424

__global__ void __launch_bounds__(256, 1) lstm_persist(
    const float* __restrict__ Wh, const float* __restrict__ h0,
    float* __restrict__ out)
{
    extern __shared__ __align__(16) char dyn[];
    uint32_t (*sWh)[40]   = reinterpret_cast<uint32_t (*)[40]>(dyn);
    float (*sH)[32][132]  = reinterpret_cast<float (*)[32][132]>(dyn + SWH_BYTES);
    float (*part)[32][40] = reinterpret_cast<float (*)[32][40]>(dyn + SWH_BYTES);

    const int tid = threadIdx.x;
    const int cta = blockIdx.x;
    const int c8  = cta * 8;
    const int chOff = cta >> 4;                // stagger: start on own cohort

    // One-time: resident Wh slice, pre-converted to tf32.
    for (int idx = tid; idx < 1024 * 32; idx += 256) {
        int row = idx >> 5, col = idx & 31;
        int q = col >> 3, jj = col & 7;
        sWh[row][col] = f2tf32(__ldg(Wh + (size_t)row * 4096 + q * 1024 + c8 + jj));
    }
    __syncthreads();

    const int warp = tid >> 5, lane = tid & 31;
    const int gid = lane >> 2, tig = lane & 3;
    const int kw = warp * 16;                  // warp's k-cols within a chunk
    const int mycol = (lane) * 4 & 127;        // this thread's fixed col in chunk
    // (tid&31)*4: 4 consecutive floats -> inside ONE producer CTA's 8-col slice
    const int bb = tid >> 3;                   // batch row 0..31 (epilogue)
    const int jb = tid & 7;                    // gate sub-col 0..7

    float creg = 0.f;

    for (int t = 0; t < 512; ++t) {
        const float* hp;
        size_t hstride;
        if (t == 0) { hp = h0;                           hstride = 1024; }
        else        { hp = out + (size_t)(t - 1) * 1024; hstride = (size_t)512 * 1024; }

        // Prefetch xproj for this thread (consumed at epilogue)
        const float* xpp = g_xproj + ((size_t)bb * 512 + t) * 4096 + c8 + jb;
        float xp0 = __ldg(xpp);
        float xp1 = __ldg(xpp + 1024);
        float xp2 = __ldg(xpp + 2048);
        float xp3 = __ldg(xpp + 3072);

        // Load chunk ch into stage s. Poll the single producer CTA of this
        // thread's column before issuing cp.async (acquire orders the reads).
        auto load_h = [&](int s, int ch) {
            const int k0 = ch * 128;
            if (t > 0) {
                const unsigned* fl = &g_flags[((k0 + mycol) >> 3) * 32];
                while (ld_acq_gpu(fl) < (unsigned)t) { }
            }
#pragma unroll
            for (int i = tid; i < 1024; i += 256) {
                int r = i >> 5;
                cp16cg(&sH[s][r][mycol], hp + (size_t)r * hstride + k0 + mycol);
            }
            cp_commit();
        };
        load_h(0, chOff & 7);
        load_h(1, (chOff + 1) & 7);
        load_h(2, (chOff + 2) & 7);

        float acc[2][4][4];
#pragma unroll
        for (int mi = 0; mi < 2; ++mi)
#pragma unroll
            for (int ni = 0; ni < 4; ++ni)
#pragma unroll
                for (int r = 0; r < 4; ++r) acc[mi][ni][r] = 0.f;

        for (int p = 0; p < 8; ++p) {
            const int cur = p & 3;
            const int ch = (p + chOff) & 7;    // actual chunk in this slot
            if (p < 6) cp_wait<2>(); else cp_wait<0>();
            __syncthreads();
            if (p < 5) load_h((p + 3) & 3, (p + 3 + chOff) & 7);

#pragma unroll
            for (int sub = 0; sub < 2; ++sub) {
                const int kk = kw + sub * 8;       // col within 128-chunk
                const int kg = ch * 128 + kk;      // global k (Wh row)
                uint32_t af[2][4], bf[4][2];
#pragma unroll
                for (int mi = 0; mi < 2; ++mi) {
                    int r = mi * 16 + gid;
                    af[mi][0] = f2tf32(sH[cur][r][kk + tig]);
                    af[mi][1] = f2tf32(sH[cur][r + 8][kk + tig]);
                    af[mi][2] = f2tf32(sH[cur][r][kk + tig + 4]);
                    af[mi][3] = f2tf32(sH[cur][r + 8][kk + tig + 4]);
                }
#pragma unroll
                for (int ni = 0; ni < 4; ++ni) {
                    bf[ni][0] = sWh[kg + tig][ni * 8 + gid];
                    bf[ni][1] = sWh[kg + tig + 4][ni * 8 + gid];
                }
#pragma unroll
                for (int mi = 0; mi < 2; ++mi)
#pragma unroll
                    for (int ni = 0; ni < 4; ++ni)
                        mma_tf32(acc[mi][ni], af[mi], bf[ni]);
            }
        }

        __syncthreads();   // all cp drained & consumed; safe to alias partials

#pragma unroll
        for (int mi = 0; mi < 2; ++mi)
#pragma unroll
            for (int ni = 0; ni < 4; ++ni) {
                int r = mi * 16 + gid, c = ni * 8 + tig * 2;
                part[warp][r][c]         = acc[mi][ni][0];
                part[warp][r][c + 1]     = acc[mi][ni][1];
                part[warp][r + 8][c]     = acc[mi][ni][2];
                part[warp][r + 8][c + 1] = acc[mi][ni][3];
            }
        __syncthreads();

        // Reduce partials + xproj -> gates -> cell -> h_t (coalesced store)
        float pre[4] = {xp0, xp1, xp2, xp3};
#pragma unroll
        for (int q = 0; q < 4; ++q) {
            int c = q * 8 + jb;
            float s = 0.f;
#pragma unroll
            for (int w = 0; w < 8; ++w) s += part[w][bb][c];
            pre[q] += s;
        }
        float ig = fast_sigmoid(pre[0]);
        float fg = fast_sigmoid(pre[1]);
        float og = fast_sigmoid(pre[2]);
        float gg = fast_tanh(pre[3]);
        creg = fg * creg + ig * gg;
        out[((size_t)bb * 512 + t) * 1024 + c8 + jb] = og * fast_tanh(creg);

        // ---- Publish: h_t slice visible -> release our flag. No barrier. ----
        __syncthreads();
        if (tid == 0) st_rel_gpu(&g_flags[cta * 32], (unsigned)(t + 1));
    }
}

// ----------------------------------------------------------------------------
extern "C" void kernel_launch(void* const* d_in, const int* in_sizes, int n_in,
                              void* d_out, int out_size)
{
    const float* x  = (const float*)d_in[0];   // (32,512,1024)
    const float* h0 = (const float*)d_in[1];   // (32,1024)
    const float* Wx = (const float*)d_in[2];   // (1024,4096)
    const float* Wh = (const float*)d_in[3];   // (1024,4096)
    const float* b  = (const float*)d_in[4];   // (4096,)
    float* out = (float*)d_out;                // (32,512,1024)

    cudaFuncSetAttribute(lstm_persist,
                         cudaFuncAttributeMaxDynamicSharedMemorySize, SMEM_BYTES);

    dim3 gA(32, 128);
    xproj_kernel<<<gA, 256>>>(x, Wx, b);
    init_kernel<<<16, 256>>>();
    lstm_persist<<<128, 256, SMEM_BYTES>>>(Wh, h0, out);
}